// round 7
// baseline (speedup 1.0000x reference)
#include <cuda_runtime.h>
#include <cstdint>

// Shapes (fixed):
//   log_probs: (128, 64) f32 | ref: (256, 128) i32 | hyp: (256, 128, 64) i32
#define NBATCH 128
#define NSAMP  64
#define NSEQ   (NBATCH * NSAMP)   // 8192
#define RLEN   256
#define HLEN   256
#define SYMS   1024               // tokens in [0,1000)
#define NW     4                  // 64-bit words per ref row (256 bits)
#define TPD    8                  // token prefetch ring depth (lane w==0)
#define NITER  (HLEN + NW - 1)    // systolic skew: 259 iterations

typedef unsigned long long ull;

__device__ double   d_partial[NBATCH];
__device__ unsigned d_ticket;      // zero-init; reset by last block each run

// ---------------------------------------------------------------------------
// One fused kernel. Block b = batch row b, 256 threads:
//   thread = (q, w): q = seq-in-batch (0..63), w = DP word (0..3).
// Systolic Myers: lane w processes DP step h = t - w at iteration t.
// Cross-word carries + tokens propagate via __shfl_up(width=4) each iteration.
// ---------------------------------------------------------------------------
__global__ void __launch_bounds__(256, 1)
mer_loss_kernel(const int* __restrict__ hyp,
                const int* __restrict__ ref,
                const float* __restrict__ logp,
                float* __restrict__ out) {
    __shared__ ull    sPeq[SYMS * NW];   // 32 KB bitmask table
    __shared__ int    sMinEos;
    __shared__ float  sEr[NSAMP];
    __shared__ bool   sLast;
    __shared__ double sSum[NBATCH];

    const int b   = blockIdx.x;
    const int tid = threadIdx.x;       // 0..255
    const int q   = tid >> 2;          // sequence within batch
    const int w   = tid & 3;           // word index
    const int n   = b * NSAMP + q;     // global sequence id

    // ---- build Peq in SMEM (tid == ref position j) ----
    if (tid == 0) sMinEos = RLEN;
    #pragma unroll
    for (int i = tid; i < SYMS * NW; i += 256) sPeq[i] = 0ull;
    __syncthreads();
    int rt = ref[(size_t)tid * NBATCH + b];
    if (rt == 0) atomicMin(&sMinEos, tid);
    __syncthreads();
    const int m = (sMinEos < RLEN) ? (sMinEos + 1) : RLEN;  // INCLUDE_EOS
    if (tid < m)
        atomicOr(&sPeq[((rt & (SYMS - 1)) << 2) + (tid >> 6)], 1ull << (tid & 63));
    __syncthreads();

    const int bsel = (m - 1) >> 6;     // word carrying the score bit
    const int pm   = (m - 1) & 63;

    // ---- per-lane DP state ----
    ull Pv = ~0ull, Mv = 0ull;
    ull phin = 1ull, mhin = 0ull;      // carry-in (word0: boundary constants)
    unsigned carry_pack = 0;           // last ACTIVE carry-out (po | mo<<1)
    int score = m;                     // meaningful on lane w==bsel
    int eos = 0;

    // token pipeline: lane w==0 owns the global load ring
    int ring[TPD];
    int tok_cur = 0;                   // token this lane processes THIS iter
    ull EqC = 0;                       // its Peq words (valid by first active iter)
    if (w == 0) {
        tok_cur = hyp[n];                                   // token[0]
        #pragma unroll
        for (int k = 0; k < TPD; ++k) ring[k] = hyp[(size_t)(k + 1) * NSEQ + n];
        EqC = sPeq[(tok_cur & (SYMS - 1)) << 2];            // word 0 of token[0]
    }

    // ---- systolic main loop ----
    #pragma unroll 1
    for (int t = 0; t < NITER; ++t) {
        // token for NEXT iteration: propagate down the skew (width-4 groups)
        int nxt = __shfl_up_sync(0xffffffffu, tok_cur, 1, 4);
        if (w == 0) {
            nxt = ring[0];
            #pragma unroll
            for (int k = 0; k < TPD - 1; ++k) ring[k] = ring[k + 1];
            int sa = t + 1 + TPD;
            ring[TPD - 1] = (sa < HLEN) ? hyp[(size_t)sa * NSEQ + n] : 0;
        }
        // prefetch next iteration's Eq word (full iteration of latency cover)
        ull EqN = sPeq[((nxt & (SYMS - 1)) << 2) + w];

        const int h = t - w;
        const int active = ((unsigned)h < (unsigned)HLEN) & (eos == 0);

        // Myers word update (identical algebra to the verified R6 kernel)
        ull Eq = EqC;
        ull Xv = Eq | Mv;
        Eq |= mhin;
        ull Xh = (((Eq & Pv) + Pv) ^ Pv) | Eq;
        ull Ph = Mv | ~(Xh | Pv);
        ull Mh = Pv & Xh;
        int sdelta = (int)((Ph >> pm) & 1ull) - (int)((Mh >> pm) & 1ull);
        unsigned po = (unsigned)(Ph >> 63);
        unsigned mo = (unsigned)(Mh >> 63);
        Ph = (Ph << 1) | phin;
        Mh = (Mh << 1) | mhin;
        ull nPv = Mh | ~(Xv | Ph);
        ull nMv = Ph & Xv;

        if (active) {
            Pv = nPv;
            Mv = nMv;
            carry_pack = po | (mo << 1);      // frozen lanes keep last active value
            if (w == bsel) score += sdelta;
            if (tok_cur == 0) eos = 1;        // EOS step processed, then freeze
        }

        // carry for NEXT iteration: lane w gets lane w-1's step-(t-w) carry-out
        unsigned cin = __shfl_up_sync(0xffffffffu, carry_pack, 1, 4);
        if (w == 0) cin = 1u;                 // phin=1, mhin=0 boundary
        phin = (ull)(cin & 1u);
        mhin = (ull)((cin >> 1) & 1u);

        EqC = EqN;
        tok_cur = nxt;
    }

    if (w == bsel) sEr[q] = (float)score / (float)m;
    __syncthreads();

    // ---- per-batch softmax-weighted centered reduction (warp 0) ----
    if (tid < 32) {
        int lane = tid, base = b * NSAMP;
        float er0 = sEr[lane],         er1 = sEr[lane + 32];
        float lp0 = logp[base + lane], lp1 = logp[base + 32 + lane];

        float mx = fmaxf(lp0, lp1);
        #pragma unroll
        for (int o = 16; o; o >>= 1) mx = fmaxf(mx, __shfl_xor_sync(0xffffffffu, mx, o));

        float e0 = expf(lp0 - mx), e1 = expf(lp1 - mx);
        float se  = e0 + e1;
        float ser = er0 + er1;
        float sep = er0 * e0 + er1 * e1;
        #pragma unroll
        for (int o = 16; o; o >>= 1) {
            se  += __shfl_xor_sync(0xffffffffu, se,  o);
            ser += __shfl_xor_sync(0xffffffffu, ser, o);
            sep += __shfl_xor_sync(0xffffffffu, sep, o);
        }
        if (lane == 0)
            d_partial[b] = (double)sep / (double)se - (double)ser / 64.0;
    }
    __syncthreads();

    // ---- last-block final reduction (threadfence-reduction pattern) ----
    if (tid == 0) {
        __threadfence();
        unsigned tk = atomicAdd(&d_ticket, 1u);
        sLast = (tk == NBATCH - 1);
    }
    __syncthreads();
    if (sLast) {
        __threadfence();
        if (tid < NBATCH) sSum[tid] = d_partial[tid];
        __syncthreads();
        #pragma unroll
        for (int o = 64; o; o >>= 1) {
            if (tid < o) sSum[tid] += sSum[tid + o];
            __syncthreads();
        }
        if (tid == 0) {
            out[0] = (float)(sSum[0] / (double)NSEQ);
            d_ticket = 0;   // reset for next graph replay (deterministic)
        }
    }
}

// ---------------------------------------------------------------------------
extern "C" void kernel_launch(void* const* d_in, const int* in_sizes, int n_in,
                              void* d_out, int out_size) {
    const float* logp = (const float*)d_in[0];  // (128,64) f32
    const int*   ref  = (const int*)d_in[1];    // (256,128) i32
    const int*   hyp  = (const int*)d_in[2];    // (256,128,64) i32
    float* out = (float*)d_out;

    mer_loss_kernel<<<NBATCH, 256>>>(hyp, ref, logp, out);
}

// round 8
// speedup vs baseline: 1.2055x; 1.2055x over previous
#include <cuda_runtime.h>
#include <cstdint>

// Shapes (fixed):
//   log_probs: (128, 64) f32 | ref: (256, 128) i32 | hyp: (256, 128, 64) i32
#define NBATCH 128
#define NSAMP  64
#define NSEQ   (NBATCH * NSAMP)   // 8192
#define RLEN   256
#define HLEN   256
#define SYMS   1024               // tokens in [0,1000)
#define TPD    6                  // token prefetch ring depth

typedef unsigned long long ull;

__device__ double   d_partial[NBATCH];
__device__ unsigned d_ticket;      // zero at start; winner resets each run

// ---------------------------------------------------------------------------
// Myers bit-parallel DP over NWA 64-bit words (NWA = words covering ref len m).
// Per-step score tracking removed: final distance recovered by masked popcount
//   D[hdone][m] = hdone + popc(Pv & mask) - popc(Mv & mask)
// hyp tokens prefetched TPD deep; next-step Peq gathered from SMEM 1 step ahead.
// ---------------------------------------------------------------------------
template<int NWA>
__device__ __forceinline__ int myers_run(const ull* __restrict__ sPeq,
                                         const int* __restrict__ hyp,
                                         int n, ull lastmask) {
    ull Pv[NWA], Mv[NWA];
    #pragma unroll
    for (int w = 0; w < NWA; ++w) { Pv[w] = ~0ull; Mv[w] = 0ull; }

    int ring[TPD];
    int t0 = hyp[n] & (SYMS - 1);
    #pragma unroll
    for (int k = 0; k < TPD; ++k) ring[k] = hyp[(size_t)(k + 1) * NSEQ + n];

    ull E[NWA];
    #pragma unroll
    for (int w = 0; w < NWA; ++w) E[w] = sPeq[(t0 << 2) + w];

    int hdone = HLEN;
    #pragma unroll 1
    for (int h = 0; h < HLEN; ++h) {
        // next step's token + its Peq words (LDS, hidden under the ALU chain)
        int t1 = ring[0] & (SYMS - 1);
        ull N[NWA];
        #pragma unroll
        for (int w = 0; w < NWA; ++w) N[w] = sPeq[(t1 << 2) + w];

        // rotate ring; issue the DRAM load TPD steps ahead
        #pragma unroll
        for (int k = 0; k < TPD - 1; ++k) ring[k] = ring[k + 1];
        int sa = h + 1 + TPD;
        ring[TPD - 1] = (sa < HLEN) ? hyp[(size_t)sa * NSEQ + n] : 0;

        ull phin = 1ull, mhin = 0ull;   // D[i][0] = i boundary
        #pragma unroll
        for (int w = 0; w < NWA; ++w) {
            ull Eq = E[w];
            ull Xv = Eq | Mv[w];
            Eq |= mhin;
            ull Xh = (((Eq & Pv[w]) + Pv[w]) ^ Pv[w]) | Eq;
            ull Ph = Mv[w] | ~(Xh | Pv[w]);
            ull Mh = Pv[w] & Xh;
            ull po = Ph >> 63, mo = Mh >> 63;
            Ph = (Ph << 1) | phin;
            Mh = (Mh << 1) | mhin;
            Pv[w] = Mh | ~(Xv | Ph);
            Mv[w] = Ph & Xv;
            phin = po; mhin = mo;
        }

        if (t0 == 0) { hdone = h + 1; break; }  // EOS step processed
        t0 = t1;
        #pragma unroll
        for (int w = 0; w < NWA; ++w) E[w] = N[w];
    }

    int score = hdone;
    #pragma unroll
    for (int w = 0; w < NWA; ++w) {
        ull mask = (w == NWA - 1) ? lastmask : ~0ull;
        score += __popcll(Pv[w] & mask) - __popcll(Mv[w] & mask);
    }
    return score;
}

// ---------------------------------------------------------------------------
// Fused kernel: block b = batch row b, 64 threads (one per sample).
// Build Peq in SMEM -> Myers per thread -> softmax-weighted centered reduction
// -> last-block ticket does the global mean.
// ---------------------------------------------------------------------------
__global__ void __launch_bounds__(NSAMP, 1)
mer_loss_kernel(const int* __restrict__ hyp,
                const int* __restrict__ ref,
                const float* __restrict__ logp,
                float* __restrict__ out) {
    __shared__ ull    sPeq[SYMS * 4];   // 32 KB bitmask table
    __shared__ int    sMinEos;
    __shared__ float  sEr[NSAMP];
    __shared__ bool   sLast;
    __shared__ double sSum[NBATCH];

    const int b = blockIdx.x;
    const int s = threadIdx.x;           // 0..63
    const int n = b * NSAMP + s;

    // ---- build Peq in SMEM ----
    if (s == 0) sMinEos = RLEN;
    #pragma unroll
    for (int i = s; i < SYMS * 4; i += NSAMP) sPeq[i] = 0ull;
    __syncthreads();

    int rtok[RLEN / NSAMP];
    #pragma unroll
    for (int k = 0; k < RLEN / NSAMP; ++k) {
        int j = s + k * NSAMP;
        rtok[k] = ref[(size_t)j * NBATCH + b];
        if (rtok[k] == 0) atomicMin(&sMinEos, j);
    }
    __syncthreads();
    const int m = (sMinEos < RLEN) ? (sMinEos + 1) : RLEN;  // INCLUDE_EOS
    #pragma unroll
    for (int k = 0; k < RLEN / NSAMP; ++k) {
        int j = s + k * NSAMP;
        if (j < m)
            atomicOr(&sPeq[((rtok[k] & (SYMS - 1)) << 2) + (j >> 6)], 1ull << (j & 63));
    }
    __syncthreads();

    const int bsel = (m - 1) >> 6;
    const int pm   = (m - 1) & 63;
    const ull lastmask = (2ull << pm) - 1ull;   // pm=63 -> ~0 (2<<63 wraps to 0)

    // ---- Myers DP, word count dispatched on uniform bsel ----
    int score;
    switch (bsel) {
        case 0:  score = myers_run<1>(sPeq, hyp, n, lastmask); break;
        case 1:  score = myers_run<2>(sPeq, hyp, n, lastmask); break;
        case 2:  score = myers_run<3>(sPeq, hyp, n, lastmask); break;
        default: score = myers_run<4>(sPeq, hyp, n, lastmask); break;
    }

    sEr[s] = (float)score / (float)m;
    __syncthreads();

    // ---- per-batch softmax-weighted centered reduction (warp 0) ----
    if (s < 32) {
        int lane = s, base = b * NSAMP;
        float er0 = sEr[lane],         er1 = sEr[lane + 32];
        float lp0 = logp[base + lane], lp1 = logp[base + 32 + lane];

        float mx = fmaxf(lp0, lp1);
        #pragma unroll
        for (int o = 16; o; o >>= 1) mx = fmaxf(mx, __shfl_xor_sync(0xffffffffu, mx, o));

        float e0 = expf(lp0 - mx), e1 = expf(lp1 - mx);
        float se  = e0 + e1;
        float ser = er0 + er1;
        float sep = er0 * e0 + er1 * e1;
        #pragma unroll
        for (int o = 16; o; o >>= 1) {
            se  += __shfl_xor_sync(0xffffffffu, se,  o);
            ser += __shfl_xor_sync(0xffffffffu, ser, o);
            sep += __shfl_xor_sync(0xffffffffu, sep, o);
        }
        if (lane == 0)
            d_partial[b] = (double)sep / (double)se - (double)ser / 64.0;
    }
    __syncthreads();

    // ---- last-block ticket: global mean ----
    if (s == 0) {
        __threadfence();
        unsigned tk = atomicAdd(&d_ticket, 1u);
        sLast = (tk == NBATCH - 1);
    }
    __syncthreads();
    if (sLast) {
        __threadfence();
        #pragma unroll
        for (int k = 0; k < NBATCH / NSAMP; ++k) sSum[s + k * NSAMP] = d_partial[s + k * NSAMP];
        __syncthreads();
        #pragma unroll
        for (int o = 64; o; o >>= 1) {
            if (s < o) sSum[s] += sSum[s + o];
            __syncthreads();
        }
        if (s == 0) {
            out[0] = (float)(sSum[0] / (double)NSEQ);
            d_ticket = 0;   // reset for next graph replay
        }
    }
}

// ---------------------------------------------------------------------------
extern "C" void kernel_launch(void* const* d_in, const int* in_sizes, int n_in,
                              void* d_out, int out_size) {
    const float* logp = (const float*)d_in[0];  // (128,64) f32
    const int*   ref  = (const int*)d_in[1];    // (256,128) i32
    const int*   hyp  = (const int*)d_in[2];    // (256,128,64) i32
    float* out = (float*)d_out;

    mer_loss_kernel<<<NBATCH, NSAMP>>>(hyp, ref, logp, out);
}

// round 10
// speedup vs baseline: 1.6947x; 1.4058x over previous
#include <cuda_runtime.h>
#include <cstdint>

// Shapes (fixed):
//   log_probs: (128, 64) f32 | ref: (256, 128) i32 | hyp: (256, 128, 64) i32
#define NBATCH 128
#define NSAMP  64
#define NSEQ   (NBATCH * NSAMP)   // 8192
#define RLEN   256
#define HLEN   256
#define SYMS   1024               // tokens in [0,1000)
#define TPD    4                  // token prefetch depth == unroll factor

typedef unsigned long long ull;

__device__ double   d_partial[NBATCH];
__device__ unsigned d_ticket;      // zero at start; winner resets each run

// ---------------------------------------------------------------------------
// Branchless Myers bit-parallel DP over NWA 64-bit words.
// Fixed 256 steps, no data-dependent branches (EOS handled by SEL capture:
// warp lanes diverging on break bought nothing — a warp runs until its
// slowest lane anyway — and the break blocked cross-step scheduling).
// Unrolled x4: token ring and E<-N copies become register renames.
// ---------------------------------------------------------------------------
template<int NWA>
__device__ __forceinline__ int myers_run(const ull* __restrict__ sPeq,
                                         const int* __restrict__ hyp,
                                         int n, int pm) {
    ull Pv[NWA], Mv[NWA];
    #pragma unroll
    for (int w = 0; w < NWA; ++w) { Pv[w] = ~0ull; Mv[w] = 0ull; }

    // token ring: toks[j] holds the (masked) token for an upcoming step
    int toks[TPD];
    int tcur = hyp[n] & (SYMS - 1);                       // token for step 0
    #pragma unroll
    for (int k = 0; k < TPD; ++k) toks[k] = hyp[(size_t)(k + 1) * NSEQ + n] & (SYMS - 1);

    ull E[NWA];
    #pragma unroll
    for (int w = 0; w < NWA; ++w) E[w] = sPeq[(tcur << 2) + w];

    int score  = 0;     // running delta vs m; caller adds m
    int scoreF = 0;
    int done   = 0;

    #pragma unroll 1
    for (int hb = 0; hb < HLEN; hb += TPD) {
        #pragma unroll
        for (int j = 0; j < TPD; ++j) {
            const int h = hb + j;

            // prefetch next step's Eq from SMEM (LDS.128 pairs)
            const int t1 = toks[j];
            ull N[NWA];
            if (NWA >= 2) {
                ulonglong2 lo = *reinterpret_cast<const ulonglong2*>(&sPeq[t1 << 2]);
                N[0] = lo.x; N[1] = lo.y;
                if (NWA == 3) N[2] = sPeq[(t1 << 2) + 2];
                if (NWA == 4) {
                    ulonglong2 hi = *reinterpret_cast<const ulonglong2*>(&sPeq[(t1 << 2) + 2]);
                    N[2] = hi.x; N[3] = hi.y;
                }
            } else {
                N[0] = sPeq[t1 << 2];
            }

            // refill ring: token for step h+1+TPD (clamped wrap; value unused
            // when h+1+TPD >= HLEN because those steps never execute)
            const int sa = (h + 1 + TPD) & (HLEN - 1);
            toks[j] = hyp[(size_t)sa * NSEQ + n] & (SYMS - 1);

            // Myers word updates (same algebra as the verified R6 kernel)
            ull phin = 1ull, mhin = 0ull;   // D[i][0] = i boundary
            #pragma unroll
            for (int w = 0; w < NWA; ++w) {
                ull Eq = E[w];
                ull Xv = Eq | Mv[w];
                Eq |= mhin;
                ull Xh = (((Eq & Pv[w]) + Pv[w]) ^ Pv[w]) | Eq;
                ull Ph = Mv[w] | ~(Xh | Pv[w]);
                ull Mh = Pv[w] & Xh;
                if (w == NWA - 1)   // score lives in the top word
                    score += (int)((Ph >> pm) & 1ull) - (int)((Mh >> pm) & 1ull);
                ull po = Ph >> 63, mo = Mh >> 63;
                Ph = (Ph << 1) | phin;
                Mh = (Mh << 1) | mhin;
                Pv[w] = Mh | ~(Xv | Ph);
                Mv[w] = Ph & Xv;
                phin = po; mhin = mo;
            }

            // branchless EOS capture: first EOS step (inclusive) latches score
            const int isEos = (tcur == 0);
            scoreF = (isEos & ~done) ? score : scoreF;
            done  |= isEos;

            tcur = t1;
            #pragma unroll
            for (int w = 0; w < NWA; ++w) E[w] = N[w];
        }
    }

    return done ? scoreF : score;
}

// ---------------------------------------------------------------------------
// Fused kernel: block b = batch row b, 64 threads (one per sample).
// ---------------------------------------------------------------------------
__global__ void __launch_bounds__(NSAMP, 1)
mer_loss_kernel(const int* __restrict__ hyp,
                const int* __restrict__ ref,
                const float* __restrict__ logp,
                float* __restrict__ out) {
    __shared__ ull    sPeq[SYMS * 4];   // 32 KB bitmask table
    __shared__ int    sMinEos;
    __shared__ float  sEr[NSAMP];
    __shared__ bool   sLast;
    __shared__ double sSum[NBATCH];

    const int b = blockIdx.x;
    const int s = threadIdx.x;           // 0..63
    const int n = b * NSAMP + s;

    // ---- build Peq in SMEM ----
    if (s == 0) sMinEos = RLEN;
    #pragma unroll
    for (int i = s; i < SYMS * 4; i += NSAMP) sPeq[i] = 0ull;
    __syncthreads();

    int rtok[RLEN / NSAMP];
    #pragma unroll
    for (int k = 0; k < RLEN / NSAMP; ++k) {
        int j = s + k * NSAMP;
        rtok[k] = ref[(size_t)j * NBATCH + b];
        if (rtok[k] == 0) atomicMin(&sMinEos, j);
    }
    __syncthreads();
    const int m = (sMinEos < RLEN) ? (sMinEos + 1) : RLEN;  // INCLUDE_EOS
    #pragma unroll
    for (int k = 0; k < RLEN / NSAMP; ++k) {
        int j = s + k * NSAMP;
        if (j < m)
            atomicOr(&sPeq[((rtok[k] & (SYMS - 1)) << 2) + (j >> 6)], 1ull << (j & 63));
    }
    __syncthreads();

    const int bsel = (m - 1) >> 6;
    const int pm   = (m - 1) & 63;

    // ---- Myers DP, word count dispatched on uniform bsel ----
    int sdel;
    switch (bsel) {
        case 0:  sdel = myers_run<1>(sPeq, hyp, n, pm); break;
        case 1:  sdel = myers_run<2>(sPeq, hyp, n, pm); break;
        case 2:  sdel = myers_run<3>(sPeq, hyp, n, pm); break;
        default: sdel = myers_run<4>(sPeq, hyp, n, pm); break;
    }
    const int score = m + sdel;

    sEr[s] = (float)score / (float)m;
    __syncthreads();

    // ---- per-batch softmax-weighted centered reduction (warp 0) ----
    if (s < 32) {
        int lane = s, base = b * NSAMP;
        float er0 = sEr[lane],         er1 = sEr[lane + 32];
        float lp0 = logp[base + lane], lp1 = logp[base + 32 + lane];

        float mx = fmaxf(lp0, lp1);
        #pragma unroll
        for (int o = 16; o; o >>= 1) mx = fmaxf(mx, __shfl_xor_sync(0xffffffffu, mx, o));

        float e0 = expf(lp0 - mx), e1 = expf(lp1 - mx);
        float se  = e0 + e1;
        float ser = er0 + er1;
        float sep = er0 * e0 + er1 * e1;
        #pragma unroll
        for (int o = 16; o; o >>= 1) {
            se  += __shfl_xor_sync(0xffffffffu, se,  o);
            ser += __shfl_xor_sync(0xffffffffu, ser, o);
            sep += __shfl_xor_sync(0xffffffffu, sep, o);
        }
        if (lane == 0)
            d_partial[b] = (double)sep / (double)se - (double)ser / 64.0;
    }
    __syncthreads();

    // ---- last-block ticket: global mean ----
    if (s == 0) {
        __threadfence();
        unsigned tk = atomicAdd(&d_ticket, 1u);
        sLast = (tk == NBATCH - 1);
    }
    __syncthreads();
    if (sLast) {
        __threadfence();
        #pragma unroll
        for (int k = 0; k < NBATCH / NSAMP; ++k) sSum[s + k * NSAMP] = d_partial[s + k * NSAMP];
        __syncthreads();
        #pragma unroll
        for (int o = 64; o; o >>= 1) {
            if (s < o) sSum[s] += sSum[s + o];
            __syncthreads();
        }
        if (s == 0) {
            out[0] = (float)(sSum[0] / (double)NSEQ);
            d_ticket = 0;   // reset for next graph replay
        }
    }
}

// ---------------------------------------------------------------------------
extern "C" void kernel_launch(void* const* d_in, const int* in_sizes, int n_in,
                              void* d_out, int out_size) {
    const float* logp = (const float*)d_in[0];  // (128,64) f32
    const int*   ref  = (const int*)d_in[1];    // (256,128) i32
    const int*   hyp  = (const int*)d_in[2];    // (256,128,64) i32
    float* out = (float*)d_out;

    mer_loss_kernel<<<NBATCH, NSAMP>>>(hyp, ref, logp, out);
}